// round 2
// baseline (speedup 1.0000x reference)
#include <cuda_runtime.h>
#include <math.h>

#define BB 8
#define TT 8
#define FNC 64
#define HW 1024
#define CG 256
#define NSTATE (BB*FNC*HW)   // 524288

// ---- persistent state ----
__device__ float g_ih[NSTATE];
__device__ float g_ic[NSTATE];
__device__ float g_im[NSTATE];
// ---- scratch ----
__device__ float g_gates[BB*CG*HW];
__device__ float g_mean[BB*8];
__device__ float g_rstd[BB*8];
__device__ float g_oh[NSTATE];
__device__ float g_qkvh[BB*192*HW];
__device__ float g_kvm[BB*128*HW];
__device__ float g_Sh[(size_t)BB*HW*HW];
__device__ float g_Sm[(size_t)BB*HW*HW];
__device__ float g_rmaxh[BB*HW], g_rinvh[BB*HW];
__device__ float g_rmaxm[BB*HW], g_rinvm[BB*HW];
__device__ float g_Zcat[BB*128*HW];
__device__ float g_Z[NSTATE];
__device__ float g_g2[BB*192*HW];
__device__ unsigned g_wT[1152*256];   // transposed+tf32 conv weights: [(ci*9+pos)][co]

__device__ __forceinline__ float sigm(float x){ return 1.f/(1.f+__expf(-x)); }

__device__ __forceinline__ unsigned f2t(float x){
  unsigned r; asm("cvt.rna.tf32.f32 %0,%1;" : "=r"(r) : "f"(x)); return r;
}

__device__ __forceinline__ void mma8(float* d, const unsigned* a, unsigned b0, unsigned b1){
  asm volatile("mma.sync.aligned.m16n8k8.row.col.f32.tf32.tf32.f32 "
    "{%0,%1,%2,%3},{%4,%5,%6,%7},{%8,%9},{%0,%1,%2,%3};"
    : "+f"(d[0]),"+f"(d[1]),"+f"(d[2]),"+f"(d[3])
    : "r"(a[0]),"r"(a[1]),"r"(a[2]),"r"(a[3]),"r"(b0),"r"(b1));
}

__global__ void zero_states(){
  int i = blockIdx.x*256 + threadIdx.x;
  if (i < NSTATE){ g_ih[i]=0.f; g_ic[i]=0.f; g_im[i]=0.f; }
}

// ---- weight transpose + tf32 convert (once per launch) ----
__global__ void wtrans(const float* __restrict__ w){
  int co = blockIdx.x;
  for (int i = threadIdx.x; i < 1152; i += 256)
    g_wT[(size_t)i*256 + co] = f2t(w[(size_t)co*1152 + i]);
}

// ------------------- 3x3 conv via implicit GEMM tensor cores -------------------
// grid (ptile=8, cot=2, b=8), block 256 (8 warps: 4 co x 2 pix)
__global__ __launch_bounds__(256) void conv_tc(const float* __restrict__ xin,
                                               const float* __restrict__ bias, int t)
{
  int pt = blockIdx.x;
  int cot = blockIdx.y;
  int b = blockIdx.z;
  int y0 = pt*4;
  int co0 = cot*128;
  __shared__ unsigned sIn[8][6][36];
  __shared__ unsigned sW[9][8][136];
  int tid = threadIdx.x;
  int warp = tid>>5, lane = tid&31, g = lane>>2, tq = lane&3;
  int wc = warp>>1, wm = warp&1;
  int pw = wm*64;
  float acc[2][8][4];
  #pragma unroll
  for(int i=0;i<2;i++)
    #pragma unroll
    for(int j=0;j<8;j++){acc[i][j][0]=0.f;acc[i][j][1]=0.f;acc[i][j][2]=0.f;acc[i][j][3]=0.f;}

  for (int chunk=0; chunk<16; chunk++){
    const float* src = (chunk<8) ? (xin + ((size_t)(b*TT+t)*64 + chunk*8)*HW)
                                 : (g_ih + ((size_t)b*64 + (chunk-8)*8)*HW);
    __syncthreads();
    for (int idx=tid; idx<8*6*34; idx+=256){
      int ci = idx/204; int r = idx-ci*204; int yy=r/34; int xx=r-yy*34;
      int gy = y0-1+yy, gx = xx-1;
      float v = 0.f;
      if ((unsigned)gy<32u && (unsigned)gx<32u) v = src[ci*HW + gy*32 + gx];
      sIn[ci][yy][xx] = f2t(v);
    }
    for (int idx=tid; idx<9216; idx+=256){
      int co = idx & 127; int r = idx >> 7;   // 0..71
      int ci = r/9; int pos = r - ci*9;
      sW[pos][ci][co] = g_wT[(size_t)((chunk*8+ci)*9+pos)*256 + co0 + co];
    }
    __syncthreads();
    #pragma unroll
    for (int pos=0; pos<9; pos++){
      int ky = pos/3, kx = pos-3*ky;
      unsigned a[2][4];
      #pragma unroll
      for (int mr=0; mr<2; mr++){
        int cb = wc*32 + mr*16;
        a[mr][0] = sW[pos][tq  ][cb+g];
        a[mr][1] = sW[pos][tq  ][cb+8+g];
        a[mr][2] = sW[pos][tq+4][cb+g];
        a[mr][3] = sW[pos][tq+4][cb+8+g];
      }
      #pragma unroll
      for (int mf=0; mf<8; mf++){
        int p = pw + mf*8 + g;
        int y = p>>5, x = p&31;
        unsigned b0 = sIn[tq  ][y+ky][x+kx];
        unsigned b1 = sIn[tq+4][y+ky][x+kx];
        mma8(acc[0][mf], a[0], b0, b1);
        mma8(acc[1][mf], a[1], b0, b1);
      }
    }
  }
  #pragma unroll
  for (int mr=0; mr<2; mr++){
    #pragma unroll
    for (int mf=0; mf<8; mf++){
      int r0 = co0 + wc*32 + mr*16 + g;
      int r1 = r0 + 8;
      int col = y0*32 + pw + mf*8 + 2*tq;
      float bv0 = bias[r0], bv1 = bias[r1];
      *(float2*)&g_gates[((size_t)b*CG + r0)*HW + col] =
          make_float2(acc[mr][mf][0]+bv0, acc[mr][mf][1]+bv0);
      *(float2*)&g_gates[((size_t)b*CG + r1)*HW + col] =
          make_float2(acc[mr][mf][2]+bv1, acc[mr][mf][3]+bv1);
    }
  }
}

// ------------------- group norm stats -------------------
__global__ void gn_stats(){
  int bg = blockIdx.x;
  int b = bg >> 3, g = bg & 7;
  const float* base = g_gates + ((size_t)b*CG + g*32)*HW;
  float s=0.f, s2=0.f;
  for (int i=threadIdx.x; i<32*HW; i+=256){ float v = base[i]; s += v; s2 += v*v; }
  __shared__ float rs[256], rq[256];
  rs[threadIdx.x]=s; rq[threadIdx.x]=s2; __syncthreads();
  for (int off=128; off; off>>=1){
    if (threadIdx.x < off){ rs[threadIdx.x]+=rs[threadIdx.x+off]; rq[threadIdx.x]+=rq[threadIdx.x+off]; }
    __syncthreads();
  }
  if (threadIdx.x==0){
    float m   = rs[0]*(1.f/32768.f);
    float var = rq[0]*(1.f/32768.f) - m*m;
    g_mean[bg] = m;
    g_rstd[bg] = rsqrtf(var + 1e-5f);
  }
}

__device__ __forceinline__ float gnormv(int b, int ch, int p,
                                        const float* __restrict__ gg,
                                        const float* __restrict__ gb){
  float v = g_gates[((size_t)b*CG + ch)*HW + p];
  int grp = ch >> 5;
  return (v - g_mean[b*8+grp]) * g_rstd[b*8+grp] * gg[ch] + gb[ch];
}

__global__ void gn_lstm(const float* __restrict__ gg, const float* __restrict__ gb){
  int idx = blockIdx.x*256 + threadIdx.x;
  int b = idx >> 16; int c = (idx >> 10) & 63; int p = idx & 1023;
  float vi = gnormv(b, c      , p, gg, gb);
  float vf = gnormv(b, c + 64 , p, gg, gb);
  float vc = gnormv(b, c + 128, p, gg, gb);
  float vo = gnormv(b, c + 192, p, gg, gb);
  float oc = g_ic[idx]*sigm(vf) + sigm(vi)*tanhf(vc);
  float oh = sigm(vo)*tanhf(oc);
  g_ic[idx] = oc;
  g_oh[idx] = oh;
}

// ------------------- 1x1 conv (GEMM, tensor cores) -------------------
// grid (b, Cout/64, pix/128), block 256 (4 co-warps x 2 pix-warps)
__global__ __launch_bounds__(256) void lin_tc(const float* __restrict__ x1, int C1,
                                              const float* __restrict__ x2, int C2,
                                              const float* __restrict__ w,
                                              const float* __restrict__ bias,
                                              float* __restrict__ y, int Cout)
{
  extern __shared__ unsigned dsm[];
  int Cin = C1 + C2;
  int pitch = Cin + 4;
  unsigned* uW = dsm;               // [64][pitch]
  unsigned* uX = dsm + 64*pitch;    // [8][136]
  int b = blockIdx.x, o0 = blockIdx.y*64, p0 = blockIdx.z*128;
  int tid=threadIdx.x, warp=tid>>5, lane=tid&31, g=lane>>2, tq=lane&3;
  int wc = warp>>1, wm = warp&1;
  for (int idx=tid; idx<64*Cin; idx+=256){
    int o = idx/Cin, c = idx - o*Cin;
    uW[o*pitch + c] = f2t(w[(size_t)(o0+o)*Cin + c]);
  }
  float acc[8][4];
  #pragma unroll
  for(int mf=0;mf<8;mf++){acc[mf][0]=0.f;acc[mf][1]=0.f;acc[mf][2]=0.f;acc[mf][3]=0.f;}
  for (int cc=0; cc<Cin; cc+=8){
    __syncthreads();
    for (int idx=tid; idx<8*128; idx+=256){
      int ci = idx>>7, m = idx&127;
      int c = cc + ci;
      float v = (c<C1) ? x1[((size_t)b*C1 + c)*HW + p0 + m]
                       : x2[((size_t)b*C2 + (c-C1))*HW + p0 + m];
      uX[ci*136 + m] = f2t(v);
    }
    __syncthreads();
    unsigned a[4];
    a[0]=uW[(wc*16+g  )*pitch + cc+tq];   a[1]=uW[(wc*16+8+g)*pitch + cc+tq];
    a[2]=uW[(wc*16+g  )*pitch + cc+tq+4]; a[3]=uW[(wc*16+8+g)*pitch + cc+tq+4];
    #pragma unroll
    for (int mf=0; mf<8; mf++){
      unsigned b0 = uX[ tq   *136 + wm*64 + mf*8 + g];
      unsigned b1 = uX[(tq+4)*136 + wm*64 + mf*8 + g];
      mma8(acc[mf], a, b0, b1);
    }
  }
  #pragma unroll
  for (int mf=0; mf<8; mf++){
    int r0 = o0 + wc*16 + g, r1 = r0 + 8;
    int col = p0 + wm*64 + mf*8 + 2*tq;
    float bv0 = bias[r0], bv1 = bias[r1];
    *(float2*)&y[((size_t)b*Cout + r0)*HW + col] = make_float2(acc[mf][0]+bv0, acc[mf][1]+bv0);
    *(float2*)&y[((size_t)b*Cout + r1)*HW + col] = make_float2(acc[mf][2]+bv1, acc[mf][3]+bv1);
  }
}

// ------------------- scores + fused row softmax stats -------------------
// S[n,m] = sum_c Q[c,n] K[c,m];  grid (b=8, ntile=8), block 256 (8 warps x 16 rows)
__global__ __launch_bounds__(256) void scores_tc(const float* __restrict__ q, int qcs,
                                                 const float* __restrict__ k, int kcs,
                                                 float* __restrict__ S,
                                                 float* __restrict__ rmax,
                                                 float* __restrict__ rinv)
{
  extern __shared__ unsigned dsm[];
  unsigned* uQ = dsm;               // [128][68]
  unsigned* uK = dsm + 128*68;      // [64][72]
  int b = blockIdx.x, n0 = blockIdx.y*128;
  int tid=threadIdx.x, warp=tid>>5, lane=tid&31, g=lane>>2, tq=lane&3;
  int nw = warp*16;
  for (int idx=tid; idx<128*64; idx+=256){
    int c = idx>>7, n = idx&127;
    uQ[n*68 + c] = f2t(q[((size_t)b*qcs + c)*HW + n0 + n]);
  }
  float M0=-1e30f, M1=-1e30f, L0=0.f, L1=0.f;
  for (int m0=0; m0<HW; m0+=64){
    __syncthreads();
    for (int idx=tid; idx<64*64; idx+=256){
      int c = idx>>6, m = idx&63;
      uK[c*72 + m] = f2t(k[((size_t)b*kcs + c)*HW + m0 + m]);
    }
    __syncthreads();
    float cfr[8][4];
    #pragma unroll
    for(int mf=0;mf<8;mf++){cfr[mf][0]=0.f;cfr[mf][1]=0.f;cfr[mf][2]=0.f;cfr[mf][3]=0.f;}
    #pragma unroll
    for (int kk=0; kk<8; kk++){
      unsigned a[4];
      a[0]=uQ[(nw+g  )*68 + kk*8+tq];   a[1]=uQ[(nw+8+g)*68 + kk*8+tq];
      a[2]=uQ[(nw+g  )*68 + kk*8+tq+4]; a[3]=uQ[(nw+8+g)*68 + kk*8+tq+4];
      #pragma unroll
      for (int mf=0; mf<8; mf++){
        unsigned b0 = uK[(kk*8+tq  )*72 + mf*8 + g];
        unsigned b1 = uK[(kk*8+tq+4)*72 + mf*8 + g];
        mma8(cfr[mf], a, b0, b1);
      }
    }
    float tm0=-1e30f, tm1=-1e30f;
    #pragma unroll
    for(int mf=0;mf<8;mf++){
      tm0 = fmaxf(tm0, fmaxf(cfr[mf][0], cfr[mf][1]));
      tm1 = fmaxf(tm1, fmaxf(cfr[mf][2], cfr[mf][3]));
    }
    tm0 = fmaxf(tm0, __shfl_xor_sync(0xffffffffu, tm0, 1));
    tm0 = fmaxf(tm0, __shfl_xor_sync(0xffffffffu, tm0, 2));
    tm1 = fmaxf(tm1, __shfl_xor_sync(0xffffffffu, tm1, 1));
    tm1 = fmaxf(tm1, __shfl_xor_sync(0xffffffffu, tm1, 2));
    float nM0 = fmaxf(M0, tm0), nM1 = fmaxf(M1, tm1);
    float s0=0.f, s1=0.f;
    #pragma unroll
    for(int mf=0;mf<8;mf++){
      s0 += __expf(cfr[mf][0]-nM0) + __expf(cfr[mf][1]-nM0);
      s1 += __expf(cfr[mf][2]-nM1) + __expf(cfr[mf][3]-nM1);
    }
    s0 += __shfl_xor_sync(0xffffffffu, s0, 1);
    s0 += __shfl_xor_sync(0xffffffffu, s0, 2);
    s1 += __shfl_xor_sync(0xffffffffu, s1, 1);
    s1 += __shfl_xor_sync(0xffffffffu, s1, 2);
    L0 = L0*__expf(M0-nM0) + s0; M0 = nM0;
    L1 = L1*__expf(M1-nM1) + s1; M1 = nM1;
    int r0 = n0+nw+g, r1 = r0+8;
    #pragma unroll
    for(int mf=0;mf<8;mf++){
      int col = m0 + mf*8 + 2*tq;
      *(float2*)&S[((size_t)b*HW + r0)*HW + col] = make_float2(cfr[mf][0], cfr[mf][1]);
      *(float2*)&S[((size_t)b*HW + r1)*HW + col] = make_float2(cfr[mf][2], cfr[mf][3]);
    }
  }
  if (tq==0){
    int r0 = n0+nw+g, r1 = r0+8;
    rmax[b*HW + r0] = M0; rinv[b*HW + r0] = 1.f/L0;
    rmax[b*HW + r1] = M1; rinv[b*HW + r1] = 1.f/L1;
  }
}

// ------------------- Z[c,m] = sum_n V[c,n]*P[n,m] (tensor cores) -------------------
// grid (b=8, mtile=8), block 256 (4 c-warps x 2 m-warps)
__global__ __launch_bounds__(256) void av_tc(const float* __restrict__ S,
                                             const float* __restrict__ rmax,
                                             const float* __restrict__ rinv,
                                             const float* __restrict__ V, int vcs,
                                             float* __restrict__ Z, int zcs, int zoff)
{
  extern __shared__ unsigned dsm[];
  unsigned* uV = dsm;             // [64][68]
  unsigned* uP = dsm + 64*68;     // [64][136]
  int b = blockIdx.x, m0 = blockIdx.y*128;
  int tid=threadIdx.x, warp=tid>>5, lane=tid&31, g=lane>>2, tq=lane&3;
  int wc = warp>>1, wm = warp&1;
  float acc[8][4];
  #pragma unroll
  for(int mf=0;mf<8;mf++){acc[mf][0]=0.f;acc[mf][1]=0.f;acc[mf][2]=0.f;acc[mf][3]=0.f;}
  for (int nb=0; nb<HW; nb+=64){
    __syncthreads();
    for (int idx=tid; idx<64*64; idx+=256){
      int c = idx>>6, n = idx&63;
      uV[c*68 + n] = f2t(V[((size_t)b*vcs + c)*HW + nb + n]);
    }
    for (int idx=tid; idx<64*128; idx+=256){
      int n = idx>>7, m = idx&127;
      int row = b*HW + nb + n;
      float p = __expf(S[(size_t)row*HW + m0 + m] - rmax[row]) * rinv[row];
      uP[n*136 + m] = f2t(p);
    }
    __syncthreads();
    #pragma unroll
    for (int kk=0; kk<8; kk++){
      unsigned a[4];
      a[0]=uV[(wc*16+g  )*68 + kk*8+tq];   a[1]=uV[(wc*16+8+g)*68 + kk*8+tq];
      a[2]=uV[(wc*16+g  )*68 + kk*8+tq+4]; a[3]=uV[(wc*16+8+g)*68 + kk*8+tq+4];
      #pragma unroll
      for (int mf=0; mf<8; mf++){
        unsigned b0 = uP[(kk*8+tq  )*136 + wm*64 + mf*8 + g];
        unsigned b1 = uP[(kk*8+tq+4)*136 + wm*64 + mf*8 + g];
        mma8(acc[mf], a, b0, b1);
      }
    }
  }
  #pragma unroll
  for (int mf=0; mf<8; mf++){
    int r0 = wc*16 + g, r1 = r0 + 8;
    int col = m0 + wm*64 + mf*8 + 2*tq;
    *(float2*)&Z[((size_t)b*zcs + zoff + r0)*HW + col] = make_float2(acc[mf][0], acc[mf][1]);
    *(float2*)&Z[((size_t)b*zcs + zoff + r1)*HW + col] = make_float2(acc[mf][2], acc[mf][3]);
  }
}

// ------------------- final gating -------------------
__global__ void final_k(float* __restrict__ out, int t, int ws){
  int idx = blockIdx.x*256 + threadIdx.x;
  int b = idx >> 16; int c = (idx >> 10) & 63; int p = idx & 1023;
  const float* g2 = g_g2 + (size_t)b*192*HW + p;
  float vo = g2[(size_t)c*HW];
  float vg = g2[(size_t)(64+c)*HW];
  float vi = g2[(size_t)(128+c)*HW];
  float si = sigm(vi);
  float om  = tanhf(vg)*si + (1.f-si)*g_im[idx];
  float oh2 = sigm(vo)*om;
  g_im[idx] = om;
  g_ih[idx] = oh2;
  out[(((size_t)b*TT + t)*FNC + c)*HW + p] = oh2;
  if (ws){
    float* st = out + (size_t)BB*TT*FNC*HW;
    st[idx]            = oh2;
    st[NSTATE + idx]   = g_ic[idx];
    st[2*NSTATE + idx] = om;
  }
}

extern "C" void kernel_launch(void* const* d_in, const int* in_sizes, int n_in,
                              void* d_out, int out_size)
{
  const float* inputs = (const float*)d_in[0];
  const float* conv_w = (const float*)d_in[1];
  const float* conv_b = (const float*)d_in[2];
  const float* gn_g   = (const float*)d_in[3];
  const float* gn_b   = (const float*)d_in[4];
  const float* h_w    = (const float*)d_in[5];
  const float* h_b    = (const float*)d_in[6];
  const float* m_w    = (const float*)d_in[7];
  const float* m_b    = (const float*)d_in[8];
  const float* z1_w   = (const float*)d_in[9];
  const float* z1_b   = (const float*)d_in[10];
  const float* z2_w   = (const float*)d_in[11];
  const float* z2_b   = (const float*)d_in[12];
  float* out = (float*)d_out;

  const int SC_SMEM = (128*68 + 64*72)*4;   // 53248
  const int AV_SMEM = (64*68 + 64*136)*4;   // 52224
  cudaFuncSetAttribute(scores_tc, cudaFuncAttributeMaxDynamicSharedMemorySize, SC_SMEM);
  cudaFuncSetAttribute(av_tc,     cudaFuncAttributeMaxDynamicSharedMemorySize, AV_SMEM);

  float *pOh, *pIm, *pQkvh, *pKvm, *pSh, *pSm, *pRmaxh, *pRinvh, *pRmaxm, *pRinvm, *pZcat, *pZ, *pG2;
  cudaGetSymbolAddress((void**)&pOh,    g_oh);
  cudaGetSymbolAddress((void**)&pIm,    g_im);
  cudaGetSymbolAddress((void**)&pQkvh,  g_qkvh);
  cudaGetSymbolAddress((void**)&pKvm,   g_kvm);
  cudaGetSymbolAddress((void**)&pSh,    g_Sh);
  cudaGetSymbolAddress((void**)&pSm,    g_Sm);
  cudaGetSymbolAddress((void**)&pRmaxh, g_rmaxh);
  cudaGetSymbolAddress((void**)&pRinvh, g_rinvh);
  cudaGetSymbolAddress((void**)&pRmaxm, g_rmaxm);
  cudaGetSymbolAddress((void**)&pRinvm, g_rinvm);
  cudaGetSymbolAddress((void**)&pZcat,  g_Zcat);
  cudaGetSymbolAddress((void**)&pZ,     g_Z);
  cudaGetSymbolAddress((void**)&pG2,    g_g2);

  zero_states<<<2048,256>>>();
  wtrans<<<256,256>>>(conv_w);
  int write_states = (out_size >= (int)(BB*TT*FNC*HW + 3*NSTATE)) ? 1 : 0;

  for (int t=0; t<TT; t++){
    conv_tc<<<dim3(8,2,8),256>>>(inputs, conv_b, t);
    gn_stats<<<64,256>>>();
    gn_lstm<<<NSTATE/256,256>>>(gn_g, gn_b);

    lin_tc<<<dim3(8,3,8),256,(64*68+8*136)*4>>>(pOh, 64, (const float*)0, 0, h_w, h_b, pQkvh, 192);
    lin_tc<<<dim3(8,2,8),256,(64*68+8*136)*4>>>(pIm, 64, (const float*)0, 0, m_w, m_b, pKvm, 128);

    scores_tc<<<dim3(8,8),256,SC_SMEM>>>(pQkvh, 192, pQkvh + (size_t)64*HW, 192, pSh, pRmaxh, pRinvh);
    scores_tc<<<dim3(8,8),256,SC_SMEM>>>(pQkvh, 192, pKvm,                  128, pSm, pRmaxm, pRinvm);

    av_tc<<<dim3(8,8),256,AV_SMEM>>>(pSh, pRmaxh, pRinvh, pQkvh + (size_t)128*HW, 192, pZcat, 128, 0);
    av_tc<<<dim3(8,8),256,AV_SMEM>>>(pSm, pRmaxm, pRinvm, pKvm  + (size_t)64*HW,  128, pZcat, 128, 64);

    lin_tc<<<dim3(8,1,8),256,(64*132+8*136)*4>>>(pZcat, 128, (const float*)0, 0, z1_w, z1_b, pZ, 64);
    lin_tc<<<dim3(8,3,8),256,(64*132+8*136)*4>>>(pZ, 64, pOh, 64, z2_w, z2_b, pG2, 192);

    final_k<<<NSTATE/256,256>>>(out, t, (t==TT-1) ? write_states : 0);
  }
}

// round 3
// speedup vs baseline: 2.9401x; 2.9401x over previous
#include <cuda_runtime.h>
#include <math.h>

#define BB 8
#define TT 8
#define HW 1024
#define CG 256
#define NSTATE (BB*64*HW)   // 524288

// ---- persistent state ----
__device__ float g_ih[NSTATE];
__device__ float g_ic[NSTATE];
__device__ float g_im[NSTATE];
// ---- scratch ----
__device__ float g_gates[BB*CG*HW];
__device__ float g_gsum [2][64];
__device__ float g_gsum2[2][64];
__device__ float g_oh[NSTATE];
__device__ float g_qkvh[BB*192*HW];
__device__ float g_kvm[BB*128*HW];
__device__ float g_rmax[2][BB*HW];
__device__ float g_rinv[2][BB*HW];
__device__ float g_Zcat[BB*128*HW];
__device__ float g_Z[NSTATE];
__device__ float g_g2[BB*192*HW];
__device__ unsigned g_wT[1152*256];   // [(ci*9+pos)][co] tf32

__device__ __forceinline__ float sigm(float x){ return 1.f/(1.f+__expf(-x)); }
__device__ __forceinline__ unsigned f2t(float x){
  unsigned r; asm("cvt.rna.tf32.f32 %0,%1;" : "=r"(r) : "f"(x)); return r;
}
__device__ __forceinline__ void mma8(float* d, const unsigned* a, unsigned b0, unsigned b1){
  asm volatile("mma.sync.aligned.m16n8k8.row.col.f32.tf32.tf32.f32 "
    "{%0,%1,%2,%3},{%4,%5,%6,%7},{%8,%9},{%0,%1,%2,%3};"
    : "+f"(d[0]),"+f"(d[1]),"+f"(d[2]),"+f"(d[3])
    : "r"(a[0]),"r"(a[1]),"r"(a[2]),"r"(a[3]),"r"(b0),"r"(b1));
}

__global__ void zero_states(){
  int i = blockIdx.x*256 + threadIdx.x;
  if (i < NSTATE){ g_ih[i]=0.f; g_ic[i]=0.f; g_im[i]=0.f; }
  if (blockIdx.x==0 && threadIdx.x<64){
    g_gsum[0][threadIdx.x]=0.f; g_gsum2[0][threadIdx.x]=0.f;
    g_gsum[1][threadIdx.x]=0.f; g_gsum2[1][threadIdx.x]=0.f;
  }
}

__global__ void wtrans(const float* __restrict__ w){
  int co = blockIdx.x;
  for (int i = threadIdx.x; i < 1152; i += 256)
    g_wT[(size_t)i*256 + co] = f2t(w[(size_t)co*1152 + i]);
}

// ------------------- 3x3 conv (implicit GEMM, TC) + fused GN partial stats ----
// grid (8 ptiles of 4 rows, 4 co-tiles of 64, 8 b), block 256
__global__ __launch_bounds__(256) void conv_tc(const float* __restrict__ xin,
                                               const float* __restrict__ bias, int t)
{
  int pt = blockIdx.x, cot = blockIdx.y, b = blockIdx.z;
  int y0 = pt*4, co0 = cot*64, par = t & 1;
  __shared__ unsigned sIn[8][6][36];
  __shared__ unsigned sW[9][8][72];
  __shared__ float ws[8], ws2[8];
  int tid=threadIdx.x, warp=tid>>5, lane=tid&31, g=lane>>2, tq=lane&3;
  int wc = warp&3, wm = warp>>2;
  float acc[8][4];
  #pragma unroll
  for(int j=0;j<8;j++){acc[j][0]=0.f;acc[j][1]=0.f;acc[j][2]=0.f;acc[j][3]=0.f;}

  for (int chunk=0; chunk<16; chunk++){
    const float* src = (chunk<8) ? (xin + ((size_t)(b*TT+t)*64 + chunk*8)*HW)
                                 : (g_ih + ((size_t)b*64 + (chunk-8)*8)*HW);
    __syncthreads();
    for (int idx=tid; idx<8*6*34; idx+=256){
      int ci = idx/204; int r = idx-ci*204; int yy=r/34; int xx=r-yy*34;
      int gy = y0-1+yy, gx = xx-1;
      float v = 0.f;
      if ((unsigned)gy<32u && (unsigned)gx<32u) v = src[ci*HW + gy*32 + gx];
      sIn[ci][yy][xx] = f2t(v);
    }
    for (int idx=tid; idx<4608; idx+=256){
      int co = idx & 63; int r = idx >> 6;  // 0..71
      int ci = r/9, pos = r - ci*9;
      sW[pos][ci][co] = g_wT[(size_t)((chunk*8+ci)*9+pos)*256 + co0 + co];
    }
    __syncthreads();
    #pragma unroll
    for (int pos=0; pos<9; pos++){
      int ky = pos/3, kx = pos-3*ky;
      unsigned a[4];
      a[0] = sW[pos][tq  ][wc*16+g];
      a[1] = sW[pos][tq  ][wc*16+8+g];
      a[2] = sW[pos][tq+4][wc*16+g];
      a[3] = sW[pos][tq+4][wc*16+8+g];
      #pragma unroll
      for (int mf=0; mf<8; mf++){
        int p = wm*64 + mf*8 + g;
        int y = p>>5, x = p&31;
        unsigned b0 = sIn[tq  ][y+ky][x+kx];
        unsigned b1 = sIn[tq+4][y+ky][x+kx];
        mma8(acc[mf], a, b0, b1);
      }
    }
  }
  int r0 = co0 + wc*16 + g, r1 = r0 + 8;
  float bv0 = bias[r0], bv1 = bias[r1];
  float s=0.f, s2=0.f;
  #pragma unroll
  for (int mf=0; mf<8; mf++){
    int col = y0*32 + wm*64 + mf*8 + 2*tq;
    float v0=acc[mf][0]+bv0, v1=acc[mf][1]+bv0;
    float v2=acc[mf][2]+bv1, v3=acc[mf][3]+bv1;
    *(float2*)&g_gates[((size_t)b*CG + r0)*HW + col] = make_float2(v0,v1);
    *(float2*)&g_gates[((size_t)b*CG + r1)*HW + col] = make_float2(v2,v3);
    s  += v0+v1+v2+v3;
    s2 += v0*v0+v1*v1+v2*v2+v3*v3;
  }
  #pragma unroll
  for (int off=16; off; off>>=1){
    s  += __shfl_xor_sync(0xffffffffu, s , off);
    s2 += __shfl_xor_sync(0xffffffffu, s2, off);
  }
  if (lane==0){ ws[warp]=s; ws2[warp]=s2; }
  __syncthreads();
  if (tid<2){
    float S  = ws [tid*2]+ws [tid*2+1]+ws [tid*2+4]+ws [tid*2+5];
    float S2 = ws2[tid*2]+ws2[tid*2+1]+ws2[tid*2+4]+ws2[tid*2+5];
    int gidx = b*8 + (co0>>5) + tid;
    atomicAdd(&g_gsum [par][gidx], S );
    atomicAdd(&g_gsum2[par][gidx], S2);
  }
}

// ------------------- GN apply + LSTM gating (inline mean/rstd) -------------------
__global__ void gn_lstm(const float* __restrict__ gg, const float* __restrict__ gb, int t){
  int idx = blockIdx.x*256 + threadIdx.x;
  int b = idx >> 16; int c = (idx >> 10) & 63; int p = idx & 1023;
  int par = t & 1;
  __shared__ float smu[4], srs[4];
  if (threadIdx.x < 4){
    int grp = (c >> 5) + threadIdx.x*2;
    float s  = g_gsum [par][b*8+grp];
    float s2 = g_gsum2[par][b*8+grp];
    float m   = s*(1.f/32768.f);
    float var = s2*(1.f/32768.f) - m*m;
    smu[threadIdx.x] = m;
    srs[threadIdx.x] = rsqrtf(var + 1e-5f);
  }
  if (blockIdx.x==0 && threadIdx.x<64){
    g_gsum[par^1][threadIdx.x]=0.f; g_gsum2[par^1][threadIdx.x]=0.f;
  }
  __syncthreads();
  const float* gt = g_gates + (size_t)b*CG*HW + p;
  float vi = (gt[(size_t)(c      )*HW] - smu[0])*srs[0]*gg[c      ] + gb[c      ];
  float vf = (gt[(size_t)(c + 64 )*HW] - smu[1])*srs[1]*gg[c + 64 ] + gb[c + 64 ];
  float vc = (gt[(size_t)(c + 128)*HW] - smu[2])*srs[2]*gg[c + 128] + gb[c + 128];
  float vo = (gt[(size_t)(c + 192)*HW] - smu[3])*srs[3]*gg[c + 192] + gb[c + 192];
  float oc = g_ic[idx]*sigm(vf) + sigm(vi)*tanhf(vc);
  float oh = sigm(vo)*tanhf(oc);
  g_ic[idx] = oc;
  g_oh[idx] = oh;
}

// ------------------- 1x1 conv (GEMM, TC), 32co x 64px tiles -------------------
// grid (b, Cout/32, 16), block 256 (2 co-warps x 4 px-warps)
__global__ __launch_bounds__(256) void lin_tc(const float* __restrict__ x1, int C1,
                                              const float* __restrict__ x2, int C2,
                                              const float* __restrict__ w,
                                              const float* __restrict__ bias,
                                              float* __restrict__ y, int Cout)
{
  __shared__ unsigned uW[32*132];
  __shared__ unsigned uX[8*72];
  int Cin = C1 + C2;
  int pitch = Cin + 4;
  int b = blockIdx.x, o0 = blockIdx.y*32, p0 = blockIdx.z*64;
  int tid=threadIdx.x, warp=tid>>5, lane=tid&31, g=lane>>2, tq=lane&3;
  int wc = warp&1, wm = warp>>1;
  for (int idx=tid; idx<32*Cin; idx+=256){
    int o = idx/Cin, c = idx - o*Cin;
    uW[o*pitch + c] = f2t(w[(size_t)(o0+o)*Cin + c]);
  }
  float acc[2][4];
  acc[0][0]=acc[0][1]=acc[0][2]=acc[0][3]=0.f;
  acc[1][0]=acc[1][1]=acc[1][2]=acc[1][3]=0.f;
  for (int cc=0; cc<Cin; cc+=8){
    __syncthreads();
    for (int idx=tid; idx<512; idx+=256){
      int ci = idx>>6, m = idx&63;
      int c = cc + ci;
      float v = (c<C1) ? x1[((size_t)b*C1 + c)*HW + p0 + m]
                       : x2[((size_t)b*C2 + (c-C1))*HW + p0 + m];
      uX[ci*72 + m] = f2t(v);
    }
    __syncthreads();
    unsigned a[4];
    a[0]=uW[(wc*16+g  )*pitch + cc+tq];   a[1]=uW[(wc*16+8+g)*pitch + cc+tq];
    a[2]=uW[(wc*16+g  )*pitch + cc+tq+4]; a[3]=uW[(wc*16+8+g)*pitch + cc+tq+4];
    #pragma unroll
    for (int mf=0; mf<2; mf++){
      unsigned b0 = uX[ tq   *72 + wm*16 + mf*8 + g];
      unsigned b1 = uX[(tq+4)*72 + wm*16 + mf*8 + g];
      mma8(acc[mf], a, b0, b1);
    }
  }
  #pragma unroll
  for (int mf=0; mf<2; mf++){
    int r0 = o0 + wc*16 + g, r1 = r0 + 8;
    int col = p0 + wm*16 + mf*8 + 2*tq;
    float bv0 = bias[r0], bv1 = bias[r1];
    *(float2*)&y[((size_t)b*Cout + r0)*HW + col] = make_float2(acc[mf][0]+bv0, acc[mf][1]+bv0);
    *(float2*)&y[((size_t)b*Cout + r1)*HW + col] = make_float2(acc[mf][2]+bv1, acc[mf][3]+bv1);
  }
}

// ------------------- pass 1: row softmax stats (no S materialization) ----------
// grid (b=8, ntile=16 of 64 rows, which=2), block 256 (4 n-warps x 2 m-warps)
__global__ __launch_bounds__(256) void qk_stats(){
  extern __shared__ unsigned dsm[];
  unsigned* uQ = dsm;            // [64n][68c]
  unsigned* uK = dsm + 64*68;    // [64c][136m]
  __shared__ float sM[2][64], sL[2][64];
  int b = blockIdx.x, n0 = blockIdx.y*64, which = blockIdx.z;
  const float* q = g_qkvh + (size_t)b*192*HW;
  const float* k = which ? (g_kvm + (size_t)b*128*HW)
                         : (g_qkvh + (size_t)b*192*HW + (size_t)64*HW);
  int tid=threadIdx.x, warp=tid>>5, lane=tid&31, g=lane>>2, tq=lane&3;
  int wn = warp&3, wm = warp>>2;
  for (int idx=tid; idx<4096; idx+=256){
    int n = idx&63, c = idx>>6;
    uQ[n*68 + c] = f2t(q[(size_t)c*HW + n0 + n]);
  }
  float M0=-1e30f, M1=-1e30f, L0=0.f, L1=0.f;
  for (int m0=0; m0<HW; m0+=128){
    __syncthreads();
    for (int idx=tid; idx<8192; idx+=256){
      int m = idx&127, c = idx>>7;
      uK[c*136 + m] = f2t(k[(size_t)c*HW + m0 + m]);
    }
    __syncthreads();
    float cfr[8][4];
    #pragma unroll
    for(int mf=0;mf<8;mf++){cfr[mf][0]=0.f;cfr[mf][1]=0.f;cfr[mf][2]=0.f;cfr[mf][3]=0.f;}
    #pragma unroll
    for (int kk=0; kk<8; kk++){
      unsigned a[4];
      a[0]=uQ[(wn*16+g  )*68 + kk*8+tq];   a[1]=uQ[(wn*16+8+g)*68 + kk*8+tq];
      a[2]=uQ[(wn*16+g  )*68 + kk*8+tq+4]; a[3]=uQ[(wn*16+8+g)*68 + kk*8+tq+4];
      #pragma unroll
      for (int mf=0; mf<8; mf++){
        unsigned b0 = uK[(kk*8+tq  )*136 + wm*64 + mf*8 + g];
        unsigned b1 = uK[(kk*8+tq+4)*136 + wm*64 + mf*8 + g];
        mma8(cfr[mf], a, b0, b1);
      }
    }
    float tm0=-1e30f, tm1=-1e30f;
    #pragma unroll
    for(int mf=0;mf<8;mf++){
      tm0 = fmaxf(tm0, fmaxf(cfr[mf][0], cfr[mf][1]));
      tm1 = fmaxf(tm1, fmaxf(cfr[mf][2], cfr[mf][3]));
    }
    tm0 = fmaxf(tm0, __shfl_xor_sync(0xffffffffu, tm0, 1));
    tm0 = fmaxf(tm0, __shfl_xor_sync(0xffffffffu, tm0, 2));
    tm1 = fmaxf(tm1, __shfl_xor_sync(0xffffffffu, tm1, 1));
    tm1 = fmaxf(tm1, __shfl_xor_sync(0xffffffffu, tm1, 2));
    float nM0 = fmaxf(M0, tm0), nM1 = fmaxf(M1, tm1);
    float s0=0.f, s1=0.f;
    #pragma unroll
    for(int mf=0;mf<8;mf++){
      s0 += __expf(cfr[mf][0]-nM0) + __expf(cfr[mf][1]-nM0);
      s1 += __expf(cfr[mf][2]-nM1) + __expf(cfr[mf][3]-nM1);
    }
    s0 += __shfl_xor_sync(0xffffffffu, s0, 1);
    s0 += __shfl_xor_sync(0xffffffffu, s0, 2);
    s1 += __shfl_xor_sync(0xffffffffu, s1, 1);
    s1 += __shfl_xor_sync(0xffffffffu, s1, 2);
    L0 = L0*__expf(M0-nM0) + s0; M0 = nM0;
    L1 = L1*__expf(M1-nM1) + s1; M1 = nM1;
  }
  if (tq==0){
    sM[wm][wn*16+g  ] = M0; sL[wm][wn*16+g  ] = L0;
    sM[wm][wn*16+8+g] = M1; sL[wm][wn*16+8+g] = L1;
  }
  __syncthreads();
  if (tid<64){
    float Ma = sM[0][tid], Mb = sM[1][tid];
    float M  = fmaxf(Ma, Mb);
    float L  = sL[0][tid]*__expf(Ma-M) + sL[1][tid]*__expf(Mb-M);
    g_rmax[which][b*HW + n0 + tid] = M;
    g_rinv[which][b*HW + n0 + tid] = 1.f/L;
  }
}

// ------------------- pass 2: recompute S tile, exp, AV GEMM ---------------------
// grid (b=8, mtile=16 of 64, which=2), block 256
__global__ __launch_bounds__(256) void av_tc(){
  extern __shared__ unsigned dsm[];
  unsigned* uK = dsm;               // [64c][72m]
  unsigned* uQ = dsm + 64*72;       // [64n][68c]
  unsigned* uV = uQ + 64*68;        // [64c][68n]
  unsigned* sP = uV + 64*68;        // [64n][72m]
  int b = blockIdx.x, m0 = blockIdx.y*64, which = blockIdx.z;
  const float* q = g_qkvh + (size_t)b*192*HW;
  const float* k = which ? (g_kvm + (size_t)b*128*HW)
                         : (g_qkvh + (size_t)b*192*HW + (size_t)64*HW);
  const float* v = which ? (g_kvm + (size_t)b*128*HW + (size_t)64*HW)
                         : (g_qkvh + (size_t)b*192*HW + (size_t)128*HW);
  const float* rmax = g_rmax[which] + b*HW;
  const float* rinv = g_rinv[which] + b*HW;
  int zoff = which*64;
  int tid=threadIdx.x, warp=tid>>5, lane=tid&31, g=lane>>2, tq=lane&3;
  int wn = warp&3, wm = warp>>2;
  for (int idx=tid; idx<4096; idx+=256){
    int m = idx&63, c = idx>>6;
    uK[c*72 + m] = f2t(k[(size_t)c*HW + m0 + m]);
  }
  float accZ[4][4];
  #pragma unroll
  for(int mf=0;mf<4;mf++){accZ[mf][0]=0.f;accZ[mf][1]=0.f;accZ[mf][2]=0.f;accZ[mf][3]=0.f;}

  for (int nb=0; nb<HW; nb+=64){
    __syncthreads();
    for (int idx=tid; idx<4096; idx+=256){
      int n = idx&63, c = idx>>6;
      uQ[n*68 + c] = f2t(q[(size_t)c*HW + nb + n]);
    }
    for (int idx=tid; idx<4096; idx+=256){
      int n = idx&63, c = idx>>6;
      uV[c*68 + n] = f2t(v[(size_t)c*HW + nb + n]);
    }
    __syncthreads();
    // GEMM1: S[n,m] tile
    float accS[4][4];
    #pragma unroll
    for(int mf=0;mf<4;mf++){accS[mf][0]=0.f;accS[mf][1]=0.f;accS[mf][2]=0.f;accS[mf][3]=0.f;}
    #pragma unroll
    for (int kk=0; kk<8; kk++){
      unsigned a[4];
      a[0]=uQ[(wn*16+g  )*68 + kk*8+tq];   a[1]=uQ[(wn*16+8+g)*68 + kk*8+tq];
      a[2]=uQ[(wn*16+g  )*68 + kk*8+tq+4]; a[3]=uQ[(wn*16+8+g)*68 + kk*8+tq+4];
      #pragma unroll
      for (int mf=0; mf<4; mf++){
        unsigned b0 = uK[(kk*8+tq  )*72 + wm*32 + mf*8 + g];
        unsigned b1 = uK[(kk*8+tq+4)*72 + wm*32 + mf*8 + g];
        mma8(accS[mf], a, b0, b1);
      }
    }
    // exp + write P to smem (tf32)
    int rb = nb + wn*16 + g;
    float rm0 = rmax[rb],   ri0 = rinv[rb];
    float rm1 = rmax[rb+8], ri1 = rinv[rb+8];
    #pragma unroll
    for (int mf=0; mf<4; mf++){
      int col = wm*32 + mf*8 + 2*tq;
      unsigned p0 = f2t(__expf(accS[mf][0]-rm0)*ri0);
      unsigned p1 = f2t(__expf(accS[mf][1]-rm0)*ri0);
      unsigned p2 = f2t(__expf(accS[mf][2]-rm1)*ri1);
      unsigned p3 = f2t(__expf(accS[mf][3]-rm1)*ri1);
      *(uint2*)&sP[(wn*16+g  )*72 + col] = make_uint2(p0,p1);
      *(uint2*)&sP[(wn*16+8+g)*72 + col] = make_uint2(p2,p3);
    }
    __syncthreads();
    // GEMM2: Z[c,m] += V[c,n] * P[n,m]
    #pragma unroll
    for (int kk=0; kk<8; kk++){
      unsigned a[4];
      a[0]=uV[(wn*16+g  )*68 + kk*8+tq];   a[1]=uV[(wn*16+8+g)*68 + kk*8+tq];
      a[2]=uV[(wn*16+g  )*68 + kk*8+tq+4]; a[3]=uV[(wn*16+8+g)*68 + kk*8+tq+4];
      #pragma unroll
      for (int mf=0; mf<4; mf++){
        unsigned b0 = sP[(kk*8+tq  )*72 + wm*32 + mf*8 + g];
        unsigned b1 = sP[(kk*8+tq+4)*72 + wm*32 + mf*8 + g];
        mma8(accZ[mf], a, b0, b1);
      }
    }
  }
  #pragma unroll
  for (int mf=0; mf<4; mf++){
    int r0 = wn*16 + g, r1 = r0 + 8;
    int col = m0 + wm*32 + mf*8 + 2*tq;
    *(float2*)&g_Zcat[((size_t)b*128 + zoff + r0)*HW + col] = make_float2(accZ[mf][0], accZ[mf][1]);
    *(float2*)&g_Zcat[((size_t)b*128 + zoff + r1)*HW + col] = make_float2(accZ[mf][2], accZ[mf][3]);
  }
}

// ------------------- final gating -------------------
__global__ void final_k(float* __restrict__ out, int t, int ws){
  int idx = blockIdx.x*256 + threadIdx.x;
  int b = idx >> 16; int c = (idx >> 10) & 63; int p = idx & 1023;
  const float* g2 = g_g2 + (size_t)b*192*HW + p;
  float vo = g2[(size_t)c*HW];
  float vg = g2[(size_t)(64+c)*HW];
  float vi = g2[(size_t)(128+c)*HW];
  float si = sigm(vi);
  float om  = tanhf(vg)*si + (1.f-si)*g_im[idx];
  float oh2 = sigm(vo)*om;
  g_im[idx] = om;
  g_ih[idx] = oh2;
  out[(((size_t)b*TT + t)*64 + c)*HW + p] = oh2;
  if (ws){
    float* st = out + (size_t)BB*TT*64*HW;
    st[idx]            = oh2;
    st[NSTATE + idx]   = g_ic[idx];
    st[2*NSTATE + idx] = om;
  }
}

extern "C" void kernel_launch(void* const* d_in, const int* in_sizes, int n_in,
                              void* d_out, int out_size)
{
  const float* inputs = (const float*)d_in[0];
  const float* conv_w = (const float*)d_in[1];
  const float* conv_b = (const float*)d_in[2];
  const float* gn_g   = (const float*)d_in[3];
  const float* gn_b   = (const float*)d_in[4];
  const float* h_w    = (const float*)d_in[5];
  const float* h_b    = (const float*)d_in[6];
  const float* m_w    = (const float*)d_in[7];
  const float* m_b    = (const float*)d_in[8];
  const float* z1_w   = (const float*)d_in[9];
  const float* z1_b   = (const float*)d_in[10];
  const float* z2_w   = (const float*)d_in[11];
  const float* z2_b   = (const float*)d_in[12];
  float* out = (float*)d_out;

  const int ST_SMEM = (64*68 + 64*136)*4;           // 52224
  const int AV_SMEM = (64*72 + 64*68*2 + 64*72)*4;  // 71680
  cudaFuncSetAttribute(qk_stats, cudaFuncAttributeMaxDynamicSharedMemorySize, ST_SMEM);
  cudaFuncSetAttribute(av_tc,    cudaFuncAttributeMaxDynamicSharedMemorySize, AV_SMEM);

  float *pOh, *pIm, *pQkvh, *pKvm, *pZcat, *pZ, *pG2;
  cudaGetSymbolAddress((void**)&pOh,   g_oh);
  cudaGetSymbolAddress((void**)&pIm,   g_im);
  cudaGetSymbolAddress((void**)&pQkvh, g_qkvh);
  cudaGetSymbolAddress((void**)&pKvm,  g_kvm);
  cudaGetSymbolAddress((void**)&pZcat, g_Zcat);
  cudaGetSymbolAddress((void**)&pZ,    g_Z);
  cudaGetSymbolAddress((void**)&pG2,   g_g2);

  zero_states<<<2048,256>>>();
  wtrans<<<256,256>>>(conv_w);
  int write_states = (out_size >= (int)(BB*TT*64*HW + 3*NSTATE)) ? 1 : 0;

  for (int t=0; t<TT; t++){
    conv_tc<<<dim3(8,4,8),256>>>(inputs, conv_b, t);
    gn_lstm<<<NSTATE/256,256>>>(gn_g, gn_b, t);

    lin_tc<<<dim3(8,6,16),256>>>(pOh, 64, (const float*)0, 0, h_w, h_b, pQkvh, 192);
    lin_tc<<<dim3(8,4,16),256>>>(pIm, 64, (const float*)0, 0, m_w, m_b, pKvm, 128);

    qk_stats<<<dim3(8,16,2),256,ST_SMEM>>>();
    av_tc  <<<dim3(8,16,2),256,AV_SMEM>>>();

    lin_tc<<<dim3(8,2,16),256>>>(pZcat, 128, (const float*)0, 0, z1_w, z1_b, pZ, 64);
    lin_tc<<<dim3(8,6,16),256>>>(pZ, 64, pOh, 64, z2_w, z2_b, pG2, 192);

    final_k<<<NSTATE/256,256>>>(out, t, (t==TT-1) ? write_states : 0);
  }
}